// round 4
// baseline (speedup 1.0000x reference)
#include <cuda_runtime.h>
#include <cstddef>
#include <cstdint>

#define B_ 512
#define T_ 1024
#define U_ 128

typedef unsigned long long ull;

// Allocation-free scratch: two 256MB staging buffers as device globals (.bss).
__device__ float g_pbuf[(size_t)T_ * B_ * U_];  // px1, later reused for p2
__device__ float g_h1[(size_t)T_ * B_ * U_];    // full h1 sequence

// ---------- packed f32x2 helpers (Blackwell FFMA2 path, PTX-only) ----------
__device__ __forceinline__ ull bc2(float v) {
    ull r; asm("mov.b64 %0, {%1,%1};" : "=l"(r) : "f"(v)); return r;
}
__device__ __forceinline__ void fma2(ull& d, ull a, ull b) {
    asm("fma.rn.f32x2 %0, %1, %2, %0;" : "+l"(d) : "l"(a), "l"(b));
}
__device__ __forceinline__ void unpk(ull v, float& lo, float& hi) {
    asm("mov.b64 {%0,%1}, %2;" : "=f"(lo), "=f"(hi) : "l"(v));
}

// ============================================================================
// Parallel GEMM + bias: out[row][u] = A_row . W[:,u] + bias[u], rows = T*B.
// Tile 64 rows x 128 units, 256 threads, thread tile 8r x 4u (f32x2-packed).
// XLAY=true: A is x with layout [b][t][k], logical row = t*B + b.
// ============================================================================
template <int KD, bool XLAY>
__global__ __launch_bounds__(256, 2)
void gemm_bias(const float* __restrict__ A, const float* __restrict__ W,
               const float* __restrict__ bias, float* __restrict__ out)
{
    extern __shared__ float sm[];
    float* Ws = sm;               // [KD][128]
    float* As = sm + KD * U_;     // [KD][68]  (68*4B = 272B rows, 16B-aligned)
    const int tid  = threadIdx.x;
    const int row0 = blockIdx.x * 64;

    for (int i = tid; i < KD * U_; i += 256) Ws[i] = W[i];

    for (int i = tid; i < 64 * KD; i += 256) {
        int r = i / KD, k = i - r * KD;
        size_t off;
        if (XLAY) {
            int t = row0 >> 9;                 // row = t*512 + b; tiles never straddle t
            int b = (row0 & (B_ - 1)) + r;
            off = ((size_t)b * T_ + t) * KD + k;
        } else {
            off = (size_t)(row0 + r) * KD + k;
        }
        As[k * 68 + r] = A[off];
    }
    __syncthreads();

    const int u0 = (tid & 31) * 4;
    const int rb = (tid >> 5) * 8;

    ull acc[4][4];
#pragma unroll
    for (int a = 0; a < 4; a++)
#pragma unroll
        for (int b = 0; b < 4; b++) acc[a][b] = 0ULL;

#pragma unroll 4
    for (int k = 0; k < KD; k++) {
        ulonglong2 a01 = *(const ulonglong2*)(As + k * 68 + rb);      // rows rb..rb+3
        ulonglong2 a23 = *(const ulonglong2*)(As + k * 68 + rb + 4);  // rows rb+4..rb+7
        float4 w4 = *(const float4*)(Ws + k * U_ + u0);
        ull w;
        w = bc2(w4.x);
        fma2(acc[0][0], a01.x, w); fma2(acc[0][1], a01.y, w);
        fma2(acc[0][2], a23.x, w); fma2(acc[0][3], a23.y, w);
        w = bc2(w4.y);
        fma2(acc[1][0], a01.x, w); fma2(acc[1][1], a01.y, w);
        fma2(acc[1][2], a23.x, w); fma2(acc[1][3], a23.y, w);
        w = bc2(w4.z);
        fma2(acc[2][0], a01.x, w); fma2(acc[2][1], a01.y, w);
        fma2(acc[2][2], a23.x, w); fma2(acc[2][3], a23.y, w);
        w = bc2(w4.w);
        fma2(acc[3][0], a01.x, w); fma2(acc[3][1], a01.y, w);
        fma2(acc[3][2], a23.x, w); fma2(acc[3][3], a23.y, w);
    }

    float f[4][8];
#pragma unroll
    for (int uu = 0; uu < 4; uu++)
#pragma unroll
        for (int rp = 0; rp < 4; rp++) unpk(acc[uu][rp], f[uu][2 * rp], f[uu][2 * rp + 1]);

    float4 bv = *(const float4*)(bias + u0);
#pragma unroll
    for (int rr = 0; rr < 8; rr++) {
        float4 o = make_float4(f[0][rr] + bv.x, f[1][rr] + bv.y,
                               f[2][rr] + bv.z, f[3][rr] + bv.w);
        *(float4*)(out + (size_t)(row0 + rb + rr) * U_ + u0) = o;
    }
}

// ============================================================================
// Recurrence: h_t = relu(p_t + h_{t-1} @ Wr), p layout [t][b][u].
// 128 CTAs x 4 independent batch rows -> no cross-CTA sync, 2 barriers/step.
// 512 thr = 128 units x 4 k-slices; Wr column slice held in REGISTERS for all t.
// STOREH: write every h_t. FINAL: emit dout[b] = h_T . Wd + bd.
// ============================================================================
template <bool STOREH, bool FINAL>
__global__ __launch_bounds__(512, 1)
void recur(const float* __restrict__ p, const float* __restrict__ Wr,
           float* __restrict__ hall, const float* __restrict__ Wd,
           const float* __restrict__ bd, float* __restrict__ dout)
{
    __shared__ float4 h_s[U_];        // h[k] packed over the 4 rows
    __shared__ float4 part_s[3 * U_]; // partials from k-slices 1..3

    const int tid = threadIdx.x;
    const int u   = tid & 127;
    const int ks  = tid >> 7;         // 0..3, each owns 32 k's
    const int r0  = blockIdx.x * 4;

    float wreg[32];
#pragma unroll
    for (int kk = 0; kk < 32; kk++) wreg[kk] = Wr[(size_t)(ks * 32 + kk) * U_ + u];

    if (ks == 0) h_s[u] = make_float4(0.f, 0.f, 0.f, 0.f);
    __syncthreads();

    const float* prow = p + (size_t)r0 * U_ + u;
    float pv0 = 0.f, pv1 = 0.f, pv2 = 0.f, pv3 = 0.f;
    if (ks == 0) { pv0 = prow[0]; pv1 = prow[U_]; pv2 = prow[2 * U_]; pv3 = prow[3 * U_]; }

    const float4* hp = h_s + ks * 32;

    for (int t = 0; t < T_; t++) {
        // prefetch next step's input term a full step ahead (hides DRAM latency)
        float nv0 = 0.f, nv1 = 0.f, nv2 = 0.f, nv3 = 0.f;
        if (ks == 0) {
            int tn = (t < T_ - 1) ? t + 1 : t;
            const float* pn = prow + (size_t)tn * B_ * U_;
            nv0 = pn[0]; nv1 = pn[U_]; nv2 = pn[2 * U_]; nv3 = pn[3 * U_];
        }

        ull a01 = 0ULL, a23 = 0ULL;   // packed rows {0,1}, {2,3}
#pragma unroll
        for (int kk = 0; kk < 32; kk++) {
            ulonglong2 hv = *(const ulonglong2*)(hp + kk);  // broadcast LDS.128
            ull w = bc2(wreg[kk]);
            fma2(a01, hv.x, w);
            fma2(a23, hv.y, w);
        }

        if (ks != 0)
            *(ulonglong2*)(part_s + (ks - 1) * U_ + u) = make_ulonglong2(a01, a23);
        __syncthreads();

        if (ks == 0) {
            float s0, s1, s2, s3;
            unpk(a01, s0, s1); unpk(a23, s2, s3);
#pragma unroll
            for (int j = 0; j < 3; j++) {
                float4 q = part_s[j * U_ + u];
                s0 += q.x; s1 += q.y; s2 += q.z; s3 += q.w;
            }
            s0 = fmaxf(s0 + pv0, 0.f); s1 = fmaxf(s1 + pv1, 0.f);
            s2 = fmaxf(s2 + pv2, 0.f); s3 = fmaxf(s3 + pv3, 0.f);
            h_s[u] = make_float4(s0, s1, s2, s3);
            if (STOREH) {
                float* ho = hall + ((size_t)t * B_ + r0) * U_ + u;
                ho[0] = s0; ho[U_] = s1; ho[2 * U_] = s2; ho[3 * U_] = s3;
            }
            pv0 = nv0; pv1 = nv1; pv2 = nv2; pv3 = nv3;
        }
        __syncthreads();
    }

    if (FINAL) {
        if (ks == 0) {
            float wd = Wd[u];
            float4 h = h_s[u];
            part_s[u] = make_float4(h.x * wd, h.y * wd, h.z * wd, h.w * wd);
        }
        __syncthreads();
        if (tid < 4) {
            float s = 0.f;
            for (int i = 0; i < U_; i++) s += ((const float*)(part_s + i))[tid];
            dout[r0 + tid] = s + bd[0];
        }
    }
}

// ============================================================================
extern "C" void kernel_launch(void* const* d_in, const int* in_sizes, int n_in,
                              void* d_out, int out_size)
{
    (void)in_sizes; (void)n_in; (void)out_size;
    const float* x   = (const float*)d_in[0];
    const float* Wx1 = (const float*)d_in[1];
    const float* Wh1 = (const float*)d_in[2];
    const float* b1  = (const float*)d_in[3];
    const float* Wx2 = (const float*)d_in[4];
    const float* Wh2 = (const float*)d_in[5];
    const float* b2  = (const float*)d_in[6];
    const float* Wd  = (const float*)d_in[7];
    const float* bd  = (const float*)d_in[8];
    float* out = (float*)d_out;

    float *pbuf, *h1buf;
    cudaGetSymbolAddress((void**)&pbuf, g_pbuf);
    cudaGetSymbolAddress((void**)&h1buf, g_h1);

    const int ngrid = (T_ * B_) / 64;                        // 8192 tiles
    const int smemA = (64 * U_ + 64 * 68) * sizeof(float);   // 50176 B
    const int smemC = (128 * U_ + 128 * 68) * sizeof(float); // 100352 B
    cudaFuncSetAttribute(gemm_bias<64, true>,
                         cudaFuncAttributeMaxDynamicSharedMemorySize, smemA);
    cudaFuncSetAttribute(gemm_bias<128, false>,
                         cudaFuncAttributeMaxDynamicSharedMemorySize, smemC);

    // Phase A: px1 = x @ Wx1 + b1           (layout [t][b][u])
    gemm_bias<64, true><<<ngrid, 256, smemA>>>(x, Wx1, b1, pbuf);
    // Phase B: h1 recurrence, store full sequence
    recur<true, false><<<B_ / 4, 512>>>(pbuf, Wh1, h1buf, nullptr, nullptr, nullptr);
    // Phase C: p2 = H1 @ Wx2 + b2           (overwrites pbuf)
    gemm_bias<128, false><<<ngrid, 256, smemC>>>(h1buf, Wx2, b2, pbuf);
    // Phase D: h2 recurrence + final projection
    recur<false, true><<<B_ / 4, 512>>>(pbuf, Wh2, nullptr, Wd, bd, out);
}

// round 6
// speedup vs baseline: 1.0004x; 1.0004x over previous
#include <cuda_runtime.h>
#include <cstddef>
#include <cstdint>

#define B_ 512
#define T_ 1024
#define U_ 128
#define RSTR 144   // padded h row stride in floats (128 + 4-per-32-block pads, 16B-aligned)

typedef unsigned long long ull;
typedef unsigned int uint;

// Allocation-free scratch: two 256MB staging buffers as device globals (.bss).
__device__ float g_pbuf[(size_t)T_ * B_ * U_];  // px1, later reused for p2
__device__ float g_h1[(size_t)T_ * B_ * U_];    // full h1 sequence

// ---------- packed f32x2 helpers (Blackwell FFMA2 path, PTX-only) ----------
__device__ __forceinline__ ull bc2(float v) {
    ull r; asm("mov.b64 %0, {%1,%1};" : "=l"(r) : "f"(v)); return r;
}
__device__ __forceinline__ ull pack2(float a, float b) {
    ull r; asm("mov.b64 %0, {%1,%2};" : "=l"(r) : "f"(a), "f"(b)); return r;
}
__device__ __forceinline__ void fma2(ull& d, ull a, ull b) {
    asm("fma.rn.f32x2 %0, %1, %2, %0;" : "+l"(d) : "l"(a), "l"(b));
}
__device__ __forceinline__ void unpk(ull v, float& lo, float& hi) {
    asm("mov.b64 {%0,%1}, %2;" : "=f"(lo), "=f"(hi) : "l"(v));
}

// ============================================================================
// Parallel GEMM + bias: out[row][u] = A_row . W[:,u] + bias[u], rows = T*B.
// Tile 64 rows x 128 units, 256 threads, thread tile 8r x 4u (f32x2-packed).
// XLAY=true: A is x with layout [b][t][k], logical row = t*B + b.
// (unchanged — known-good from the R4 passing run)
// ============================================================================
template <int KD, bool XLAY>
__global__ __launch_bounds__(256, 2)
void gemm_bias(const float* __restrict__ A, const float* __restrict__ W,
               const float* __restrict__ bias, float* __restrict__ out)
{
    extern __shared__ float sm[];
    float* Ws = sm;               // [KD][128]
    float* As = sm + KD * U_;     // [KD][68]
    const int tid  = threadIdx.x;
    const int row0 = blockIdx.x * 64;

    for (int i = tid; i < KD * U_; i += 256) Ws[i] = W[i];

    for (int i = tid; i < 64 * KD; i += 256) {
        int r = i / KD, k = i - r * KD;
        size_t off;
        if (XLAY) {
            int t = row0 >> 9;
            int b = (row0 & (B_ - 1)) + r;
            off = ((size_t)b * T_ + t) * KD + k;
        } else {
            off = (size_t)(row0 + r) * KD + k;
        }
        As[k * 68 + r] = A[off];
    }
    __syncthreads();

    const int u0 = (tid & 31) * 4;
    const int rb = (tid >> 5) * 8;

    ull acc[4][4];
#pragma unroll
    for (int a = 0; a < 4; a++)
#pragma unroll
        for (int b = 0; b < 4; b++) acc[a][b] = 0ULL;

#pragma unroll 4
    for (int k = 0; k < KD; k++) {
        ulonglong2 a01 = *(const ulonglong2*)(As + k * 68 + rb);
        ulonglong2 a23 = *(const ulonglong2*)(As + k * 68 + rb + 4);
        float4 w4 = *(const float4*)(Ws + k * U_ + u0);
        ull w;
        w = bc2(w4.x);
        fma2(acc[0][0], a01.x, w); fma2(acc[0][1], a01.y, w);
        fma2(acc[0][2], a23.x, w); fma2(acc[0][3], a23.y, w);
        w = bc2(w4.y);
        fma2(acc[1][0], a01.x, w); fma2(acc[1][1], a01.y, w);
        fma2(acc[1][2], a23.x, w); fma2(acc[1][3], a23.y, w);
        w = bc2(w4.z);
        fma2(acc[2][0], a01.x, w); fma2(acc[2][1], a01.y, w);
        fma2(acc[2][2], a23.x, w); fma2(acc[2][3], a23.y, w);
        w = bc2(w4.w);
        fma2(acc[3][0], a01.x, w); fma2(acc[3][1], a01.y, w);
        fma2(acc[3][2], a23.x, w); fma2(acc[3][3], a23.y, w);
    }

    float f[4][8];
#pragma unroll
    for (int uu = 0; uu < 4; uu++)
#pragma unroll
        for (int rp = 0; rp < 4; rp++) unpk(acc[uu][rp], f[uu][2 * rp], f[uu][2 * rp + 1]);

    float4 bv = *(const float4*)(bias + u0);
#pragma unroll
    for (int rr = 0; rr < 8; rr++) {
        float4 o = make_float4(f[0][rr] + bv.x, f[1][rr] + bv.y,
                               f[2][rr] + bv.z, f[3][rr] + bv.w);
        *(float4*)(out + (size_t)(row0 + rb + rr) * U_ + u0) = o;
    }
}

// ============================================================================
// Recurrence v2: h_t = relu(p_t + h_{t-1} @ Wr), p layout [t][b][u].
// 128 CTAs x 4 independent batch rows. 256 threads: u = tid>>1, ks = tid&1
// (two 64-k slices per unit, SAME WARP adjacent lanes -> shfl reduction).
// Weights pre-packed as f32x2 k-pairs in registers (zero per-step packing).
// h state ping-pong buffers -> exactly ONE barrier per step.
// Padded h layout: k_phys = k + 4*(k>>5) -> the four (ks,half) load groups
// hit distinct 4-bank spans: conflict-free broadcast LDS.128.
// ============================================================================
template <bool STOREH, bool FINAL>
__global__ __launch_bounds__(256, 1)
void recur2(const float* __restrict__ p, const float* __restrict__ Wr,
            float* __restrict__ hall, const float* __restrict__ Wd,
            const float* __restrict__ bd, float* __restrict__ dout)
{
    __shared__ __align__(16) float hs[2][4 * RSTR];
    __shared__ float4 part_s[U_];

    const int tid = threadIdx.x;
    const int u   = tid >> 1;
    const int ks  = tid & 1;          // which 64-k slice
    const int r0  = blockIdx.x * 4;
    const bool wr = (ks == 0);

    // 32 packed weight pairs {w[k],w[k+1]} for k = ks*64 .. ks*64+63 (loaded ONCE)
    ull wp[32];
#pragma unroll
    for (int i = 0; i < 32; i++) {
        float a = Wr[(size_t)(ks * 64 + 2 * i) * U_ + u];
        float b = Wr[(size_t)(ks * 64 + 2 * i + 1) * U_ + u];
        wp[i] = pack2(a, b);
    }

    // zero initial read buffer (buffer 0)
    for (int i = tid; i < 4 * RSTR; i += 256) hs[0][i] = 0.f;

    const int uph = u + 4 * (u >> 5);             // padded h index for writes

    const float* prow = p + (size_t)r0 * U_ + u;
    float pv[4] = {0.f, 0.f, 0.f, 0.f};
    if (wr) { pv[0] = prow[0]; pv[1] = prow[U_]; pv[2] = prow[2 * U_]; pv[3] = prow[3 * U_]; }
    __syncthreads();

    const int ksoff = ks * 72;                    // slice base in padded floats

    for (int t = 0; t < T_; t++) {
        // prefetch next step's p one full step ahead (writers only)
        float pn[4] = {0.f, 0.f, 0.f, 0.f};
        if (wr) {
            int tn = (t < T_ - 1) ? t + 1 : t;
            const float* pp = prow + (size_t)tn * B_ * U_;
            pn[0] = pp[0]; pn[1] = pp[U_]; pn[2] = pp[2 * U_]; pn[3] = pp[3 * U_];
        }

        const float* hb = hs[t & 1];
        float*       hn = hs[(t + 1) & 1];

        ull acc[4] = {0ULL, 0ULL, 0ULL, 0ULL};
#pragma unroll
        for (int r = 0; r < 4; r++) {
            const char* base = (const char*)(hb + r * RSTR + ksoff);
#pragma unroll
            for (int half = 0; half < 2; half++) {
#pragma unroll
                for (int i = 0; i < 8; i++) {
                    ulonglong2 hv = *(const ulonglong2*)(base + half * 144 + i * 16);
                    fma2(acc[r], hv.x, wp[half * 16 + 2 * i]);
                    fma2(acc[r], hv.y, wp[half * 16 + 2 * i + 1]);
                }
            }
        }

        // cross-slice reduction via one shfl.bfly round (partner = lane^1)
        float s[4];
#pragma unroll
        for (int r = 0; r < 4; r++) {
            uint lo = (uint)acc[r], hi = (uint)(acc[r] >> 32);
            uint plo = __shfl_xor_sync(0xffffffffu, lo, 1);
            uint phi = __shfl_xor_sync(0xffffffffu, hi, 1);
            float flo = __uint_as_float(lo) + __uint_as_float(plo);
            float fhi = __uint_as_float(hi) + __uint_as_float(phi);
            s[r] = fmaxf(flo + fhi + pv[r], 0.f);
        }

        if (wr) {
#pragma unroll
            for (int r = 0; r < 4; r++) {
                hn[r * RSTR + uph] = s[r];
                if (STOREH)
                    hall[((size_t)t * B_ + r0 + r) * U_ + u] = s[r];
                pv[r] = pn[r];
            }
        }
        __syncthreads();   // single barrier: next step reads hn
    }

    if (FINAL) {
        // final h lives in hs[0] (T even). out[b] = h . Wd + bd
        if (wr) {
            float wd = Wd[u];
            const float* hf = hs[0];
            part_s[u] = make_float4(hf[0 * RSTR + uph] * wd, hf[1 * RSTR + uph] * wd,
                                    hf[2 * RSTR + uph] * wd, hf[3 * RSTR + uph] * wd);
        }
        __syncthreads();
        if (tid < 4) {
            float ssum = 0.f;
            for (int i = 0; i < U_; i++) ssum += ((const float*)(part_s + i))[tid];
            dout[r0 + tid] = ssum + bd[0];
        }
    }
}

// ============================================================================
extern "C" void kernel_launch(void* const* d_in, const int* in_sizes, int n_in,
                              void* d_out, int out_size)
{
    (void)in_sizes; (void)n_in; (void)out_size;
    const float* x   = (const float*)d_in[0];
    const float* Wx1 = (const float*)d_in[1];
    const float* Wh1 = (const float*)d_in[2];
    const float* b1  = (const float*)d_in[3];
    const float* Wx2 = (const float*)d_in[4];
    const float* Wh2 = (const float*)d_in[5];
    const float* b2  = (const float*)d_in[6];
    const float* Wd  = (const float*)d_in[7];
    const float* bd  = (const float*)d_in[8];
    float* out = (float*)d_out;

    float *pbuf, *h1buf;
    cudaGetSymbolAddress((void**)&pbuf, g_pbuf);
    cudaGetSymbolAddress((void**)&h1buf, g_h1);

    const int ngrid = (T_ * B_) / 64;                        // 8192 tiles
    const int smemA = (64 * U_ + 64 * 68) * sizeof(float);   // 50176 B
    const int smemC = (128 * U_ + 128 * 68) * sizeof(float); // 100352 B
    cudaFuncSetAttribute(gemm_bias<64, true>,
                         cudaFuncAttributeMaxDynamicSharedMemorySize, smemA);
    cudaFuncSetAttribute(gemm_bias<128, false>,
                         cudaFuncAttributeMaxDynamicSharedMemorySize, smemC);

    // Phase A: px1 = x @ Wx1 + b1           (layout [t][b][u])
    gemm_bias<64, true><<<ngrid, 256, smemA>>>(x, Wx1, b1, pbuf);
    // Phase B: h1 recurrence, store full sequence
    recur2<true, false><<<B_ / 4, 256>>>(pbuf, Wh1, h1buf, nullptr, nullptr, nullptr);
    // Phase C: p2 = H1 @ Wx2 + b2           (overwrites pbuf)
    gemm_bias<128, false><<<ngrid, 256, smemC>>>(h1buf, Wx2, b2, pbuf);
    // Phase D: h2 recurrence + final projection
    recur2<false, true><<<B_ / 4, 256>>>(pbuf, Wh2, nullptr, Wd, bd, out);
}